// round 13
// baseline (speedup 1.0000x reference)
#include <cuda_runtime.h>

// D fixed by the problem (256 floats per row).
#define D     256
#define TPB   128
#define WPB   (TPB / 32)
#define NBLK  1064            // 152 SMs x 7 resident blocks: one persistent wave

// Per-block partial sums (every slot written every call -> no zeroing needed).
__device__ double   d_part[NBLK];
// Completion counter: 0 at start, last block resets it -> replay-deterministic.
__device__ unsigned d_count;

__device__ __forceinline__ float dot4(float4 a, float4 b) {
    return a.x * b.x + a.y * b.y + a.z * b.z + a.w * b.w;
}

// ---------------------------------------------------------------------------
// Persistent single-wave kernel, HALF-DEPTH software pipeline at 7 blocks/SM:
//   - next pair's row-a loads (4x LDG.128) issue before the shuffle phase
//   - next pair's row-b loads issue at loop bottom, ahead of their use
// so loads stay outstanding through the reduction without blowing the
// 72-register budget that keeps 28 warps/SM resident.
//   total = sum_i  dot(h1_i, g2_b)*ginv(h1_i)*ginv(g2_b)
//               +  dot(h2_i, g1_b)*ginv(h2_i)*ginv(g1_b),   b = batch[i]
// batch is sorted: the two 1 KB g rows live in registers, reloaded only on
// (rare) b change; inverse norms computed inline then.
// ---------------------------------------------------------------------------
__global__ void __launch_bounds__(TPB, 7)
main_k(const float* __restrict__ h1, const float* __restrict__ h2,
       const float* __restrict__ g1, const float* __restrict__ g2,
       const int*   __restrict__ batch, float* __restrict__ out,
       int N, int G)
{
    const int lane  = threadIdx.x & 31;
    const int wid   = threadIdx.x >> 5;
    const int gwarp = blockIdx.x * WPB + wid;
    const int nw    = gridDim.x * WPB;

    const int per = (N + nw - 1) / nw;
    const int i0  = gwarp * per;
    const int i1  = min(N, i0 + per);

    double acc = 0.0;

    int   bcur = -1;
    float gi1 = 0.f, gi2 = 0.f;               // lane-uniform inverse norms
    float4 fg0, fg1, cg0, cg1;                // cached g1/g2 rows (lane slice)
    fg0 = fg1 = cg0 = cg1 = make_float4(0.f, 0.f, 0.f, 0.f);

#define RELOAD_G(B)                                                          \
    do {                                                                     \
        bcur = (B);                                                          \
        const float4* pg1 = reinterpret_cast<const float4*>(g1 + (size_t)bcur * D); \
        const float4* pg2 = reinterpret_cast<const float4*>(g2 + (size_t)bcur * D); \
        fg0 = pg1[lane]; fg1 = pg1[lane + 32];                               \
        cg0 = pg2[lane]; cg1 = pg2[lane + 32];                               \
        float sg1 = dot4(fg0, fg0) + dot4(fg1, fg1);                         \
        float sg2 = dot4(cg0, cg0) + dot4(cg1, cg1);                         \
        _Pragma("unroll")                                                    \
        for (int off = 16; off > 0; off >>= 1) {                             \
            sg1 += __shfl_xor_sync(0xffffffffu, sg1, off);                   \
            sg2 += __shfl_xor_sync(0xffffffffu, sg2, off);                   \
        }                                                                    \
        gi1 = rsqrtf(fmaxf(sg1, 1e-24f));                                    \
        gi2 = rsqrtf(fmaxf(sg2, 1e-24f));                                    \
    } while (0)

#define LOAD_A(I)                                                            \
    do {                                                                     \
        const float4* pa1 = reinterpret_cast<const float4*>(h1 + (size_t)(I) * D); \
        const float4* pa2 = reinterpret_cast<const float4*>(h2 + (size_t)(I) * D); \
        a0 = __ldcs(pa1 + lane); a1 = __ldcs(pa1 + lane + 32);               \
        e0 = __ldcs(pa2 + lane); e1 = __ldcs(pa2 + lane + 32);               \
    } while (0)

#define LOAD_B(I)                                                            \
    do {                                                                     \
        const float4* pb1 = reinterpret_cast<const float4*>(h1 + (size_t)((I) + 1) * D); \
        const float4* pb2 = reinterpret_cast<const float4*>(h2 + (size_t)((I) + 1) * D); \
        b0 = __ldcs(pb1 + lane); b1 = __ldcs(pb1 + lane + 32);               \
        f0 = __ldcs(pb2 + lane); f1 = __ldcs(pb2 + lane + 32);               \
    } while (0)

    float4 a0, a1, e0, e1, b0, b1, f0, f1;
    int i  = i0;
    int ba = 0, bb = 0;
    bool have = (i + 1 < i1);                 // a full pair exists
    if (have) {                               // prologue: load pair i fully
        ba = batch[i]; bb = batch[i + 1];
        LOAD_A(i); LOAD_B(i);
    }

    while (have) {
        const int  ni    = i + 2;
        const bool nhave = (ni + 1 < i1);

        // ---- consume current pair's data into 8 dot scalars ----
        if (ba != bcur) RELOAD_G(ba);         // warp-uniform, rare
        const float gia1 = gi1, gia2 = gi2;   // snapshot for row a

        float da1 = dot4(a0, cg0) + dot4(a1, cg1);
        float sa1 = dot4(a0, a0)  + dot4(a1, a1);
        float da2 = dot4(e0, fg0) + dot4(e1, fg1);
        float sa2 = dot4(e0, e0)  + dot4(e1, e1);

        if (bb != bcur) RELOAD_G(bb);         // sorted: ba <= bb

        float db1 = dot4(b0, cg0) + dot4(b1, cg1);
        float sb1 = dot4(b0, b0)  + dot4(b1, b1);
        float db2 = dot4(f0, fg0) + dot4(f1, fg1);
        float sb2 = dot4(f0, f0)  + dot4(f1, f1);

        // ---- A-half prefetch of next pair: in flight during reductions ----
        int nba = ba, nbb = bb;
        if (nhave) {
            nba = batch[ni]; nbb = batch[ni + 1];
            LOAD_A(ni);                       // overwrites dead a0,a1,e0,e1
        }

        // ---- 8 interleaved butterfly chains (A-half loads overlapping) ----
#pragma unroll
        for (int off = 16; off > 0; off >>= 1) {
            da1 += __shfl_xor_sync(0xffffffffu, da1, off);
            sa1 += __shfl_xor_sync(0xffffffffu, sa1, off);
            da2 += __shfl_xor_sync(0xffffffffu, da2, off);
            sa2 += __shfl_xor_sync(0xffffffffu, sa2, off);
            db1 += __shfl_xor_sync(0xffffffffu, db1, off);
            sb1 += __shfl_xor_sync(0xffffffffu, sb1, off);
            db2 += __shfl_xor_sync(0xffffffffu, db2, off);
            sb2 += __shfl_xor_sync(0xffffffffu, sb2, off);
        }

        const float va = da1 * rsqrtf(fmaxf(sa1, 1e-24f)) * gia2
                       + da2 * rsqrtf(fmaxf(sa2, 1e-24f)) * gia1;
        const float vb = db1 * rsqrtf(fmaxf(sb1, 1e-24f)) * gi2
                       + db2 * rsqrtf(fmaxf(sb2, 1e-24f)) * gi1;
        acc += (double)va;
        acc += (double)vb;

        // ---- B-half prefetch of next pair: ~100 cyc ahead of its use ----
        if (nhave) LOAD_B(ni);                // overwrites dead b0,b1,f0,f1

        i = ni; ba = nba; bb = nbb; have = nhave;
    }

    if (i < i1) {                              // odd remainder row
        const int b = batch[i];
        const float4* ph1 = reinterpret_cast<const float4*>(h1 + (size_t)i * D);
        const float4* ph2 = reinterpret_cast<const float4*>(h2 + (size_t)i * D);
        float4 x0 = __ldcs(ph1 + lane), x1 = __ldcs(ph1 + lane + 32);
        float4 y0 = __ldcs(ph2 + lane), y1 = __ldcs(ph2 + lane + 32);

        if (b != bcur) RELOAD_G(b);

        float d1 = dot4(x0, cg0) + dot4(x1, cg1);
        float s1 = dot4(x0, x0)  + dot4(x1, x1);
        float d2 = dot4(y0, fg0) + dot4(y1, fg1);
        float s2 = dot4(y0, y0)  + dot4(y1, y1);
#pragma unroll
        for (int off = 16; off > 0; off >>= 1) {
            d1 += __shfl_xor_sync(0xffffffffu, d1, off);
            s1 += __shfl_xor_sync(0xffffffffu, s1, off);
            d2 += __shfl_xor_sync(0xffffffffu, d2, off);
            s2 += __shfl_xor_sync(0xffffffffu, s2, off);
        }
        const float v = d1 * rsqrtf(fmaxf(s1, 1e-24f)) * gi2
                      + d2 * rsqrtf(fmaxf(s2, 1e-24f)) * gi1;
        acc += (double)v;
    }
#undef LOAD_A
#undef LOAD_B
#undef RELOAD_G

    // ---- block-level partial ----
    __shared__ double sred[WPB];
    __shared__ bool   is_last;
    if (lane == 0) sred[wid] = acc;
    __syncthreads();
    if (threadIdx.x == 0) {
        double t = 0.0;
#pragma unroll
        for (int w = 0; w < WPB; ++w) t += sred[w];
        d_part[blockIdx.x] = t;
        __threadfence();
        unsigned prev = atomicAdd(&d_count, 1u);
        is_last = (prev == (unsigned)(NBLK - 1));
    }
    __syncthreads();

    // ---- last block: fixed-order deterministic final reduction ----
    if (is_last) {
        __shared__ double s[TPB];
        double t = 0.0;
        for (int k = threadIdx.x; k < NBLK; k += TPB)
            t += __ldcg(&d_part[k]);
        s[threadIdx.x] = t;
        __syncthreads();
#pragma unroll
        for (int off = TPB / 2; off > 0; off >>= 1) {
            if (threadIdx.x < off) s[threadIdx.x] += s[threadIdx.x + off];
            __syncthreads();
        }
        if (threadIdx.x == 0) {
            *out = (float)(s[0] / (double)G);
            d_count = 0;                       // reset for next graph replay
        }
    }
}

extern "C" void kernel_launch(void* const* d_in, const int* in_sizes, int n_in,
                              void* d_out, int out_size)
{
    const float* h1    = (const float*)d_in[0];
    const float* h2    = (const float*)d_in[1];
    const float* g1    = (const float*)d_in[2];
    const float* g2    = (const float*)d_in[3];
    const int*   batch = (const int*)d_in[4];   // jax default int32 (x64 disabled)

    const int N = in_sizes[4];          // rows in h1/h2
    const int G = in_sizes[2] / D;      // rows in g1/g2

    main_k<<<NBLK, TPB>>>(h1, h2, g1, g2, batch, (float*)d_out, N, G);
}

// round 14
// speedup vs baseline: 1.0712x; 1.0712x over previous
#include <cuda_runtime.h>

// D fixed by the problem (256 floats per row).
#define D     256
#define D4    64              // float4s per row
#define TPB   128
#define WPB   (TPB / 32)
#define NBLK  1216            // 152 SMs x 8 resident blocks: one persistent wave

// Per-block partial sums (every slot written every call -> no zeroing needed).
__device__ double   d_part[NBLK];
// Completion counter: 0 at start, last block resets it -> replay-deterministic.
__device__ unsigned d_count;

__device__ __forceinline__ float dot4(float4 a, float4 b) {
    return a.x * b.x + a.y * b.y + a.z * b.z + a.w * b.w;
}

// ---------------------------------------------------------------------------
// Persistent single-wave kernel, HALF-WARP row mapping:
//   lanes 0-15 process row i, lanes 16-31 process row i+1 (16 floats per
//   lane per tensor). Both rows' reductions share the SAME 4-stage butterfly
//   instructions (offsets 8,4,2,1): 16 SHFL per row pair instead of 40.
// The g1/g2 rows are parked in per-lane shared-memory slots (each lane reads
// only chunks it wrote -> no syncs, no conflicts), freeing registers so all
// 8 h-loads stay front-batched at 32 warps/SM with zero spills.
//   total = sum_i  dot(h1_i, g2_b)*ginv(h1_i)*ginv(g2_b)
//               +  dot(h2_i, g1_b)*ginv(h2_i)*ginv(g1_b),   b = batch[i]
// ---------------------------------------------------------------------------
__global__ void __launch_bounds__(TPB, 8)
main_k(const float* __restrict__ h1, const float* __restrict__ h2,
       const float* __restrict__ g1, const float* __restrict__ g2,
       const int*   __restrict__ batch, float* __restrict__ out,
       int N, int G)
{
    const int lane = threadIdx.x & 31;
    const int wid  = threadIdx.x >> 5;
    const int hw   = lane >> 4;           // half-warp id (row selector)
    const int hl   = lane & 15;           // lane within half-warp
    const int gwarp = blockIdx.x * WPB + wid;
    const int nw    = gridDim.x * WPB;

    const int per = (N + nw - 1) / nw;
    const int i0  = gwarp * per;
    const int i1  = min(N, i0 + per);

    // [warp][half][tensor][chunk]: 4*2*2*64 float4 = 16 KB / block.
    __shared__ float4 gsm[WPB][2][2][D4];

    double acc = 0.0;
    int   bcur = -1;                      // half-warp-uniform
    float gi1 = 0.f, gi2 = 0.f;           // inverse norms for this half's b

    int i = i0;
    for (; i + 1 < i1; i += 2) {
        const int b = batch[i + hw];      // half0 -> row i, half1 -> row i+1

        // Warp-uniform trigger (ballot) so shuffles below are full-warp safe;
        // halves whose b didn't change just refresh from L1 (rare, harmless).
        if (__ballot_sync(0xffffffffu, b != bcur)) {
            bcur = b;
            const float4* pg1 = reinterpret_cast<const float4*>(g1) + (size_t)b * D4;
            const float4* pg2 = reinterpret_cast<const float4*>(g2) + (size_t)b * D4;
            float sg1 = 0.f, sg2 = 0.f;
#pragma unroll
            for (int j = 0; j < 4; ++j) {
                float4 u = pg1[hl + 16 * j];
                float4 w = pg2[hl + 16 * j];
                gsm[wid][hw][0][hl + 16 * j] = u;
                gsm[wid][hw][1][hl + 16 * j] = w;
                sg1 += dot4(u, u);
                sg2 += dot4(w, w);
            }
#pragma unroll
            for (int off = 8; off > 0; off >>= 1) {   // per-half reduction
                sg1 += __shfl_xor_sync(0xffffffffu, sg1, off);
                sg2 += __shfl_xor_sync(0xffffffffu, sg2, off);
            }
            // 1/max(||g||,1e-12) == rsqrt(max(s,1e-24)) at these magnitudes
            gi1 = rsqrtf(fmaxf(sg1, 1e-24f));
            gi2 = rsqrtf(fmaxf(sg2, 1e-24f));
        }

        // 8 front-batched h loads (MLP=8), evict-first streaming.
        const float4* p1 = reinterpret_cast<const float4*>(h1) + (size_t)(i + hw) * D4;
        const float4* p2 = reinterpret_cast<const float4*>(h2) + (size_t)(i + hw) * D4;
        float4 x0 = __ldcs(p1 + hl),      x1 = __ldcs(p1 + hl + 16),
               x2 = __ldcs(p1 + hl + 32), x3 = __ldcs(p1 + hl + 48);
        float4 y0 = __ldcs(p2 + hl),      y1 = __ldcs(p2 + hl + 16),
               y2 = __ldcs(p2 + hl + 32), y3 = __ldcs(p2 + hl + 48);

        // Dots: g chunks come back from this lane's own smem slot.
        float d1 = dot4(x0, gsm[wid][hw][1][hl])
                 + dot4(x1, gsm[wid][hw][1][hl + 16])
                 + dot4(x2, gsm[wid][hw][1][hl + 32])
                 + dot4(x3, gsm[wid][hw][1][hl + 48]);
        float s1 = dot4(x0, x0) + dot4(x1, x1) + dot4(x2, x2) + dot4(x3, x3);
        float d2 = dot4(y0, gsm[wid][hw][0][hl])
                 + dot4(y1, gsm[wid][hw][0][hl + 16])
                 + dot4(y2, gsm[wid][hw][0][hl + 32])
                 + dot4(y3, gsm[wid][hw][0][hl + 48]);
        float s2 = dot4(y0, y0) + dot4(y1, y1) + dot4(y2, y2) + dot4(y3, y3);

        // 4-stage butterfly, both halves reduce on the same instructions.
#pragma unroll
        for (int off = 8; off > 0; off >>= 1) {
            d1 += __shfl_xor_sync(0xffffffffu, d1, off);
            s1 += __shfl_xor_sync(0xffffffffu, s1, off);
            d2 += __shfl_xor_sync(0xffffffffu, d2, off);
            s2 += __shfl_xor_sync(0xffffffffu, s2, off);
        }

        const float v = d1 * rsqrtf(fmaxf(s1, 1e-24f)) * gi2
                      + d2 * rsqrtf(fmaxf(s2, 1e-24f)) * gi1;
        if (hl == 0) acc += (double)v;    // one accumulator per half-warp
    }

    if (i < i1) {                          // odd remainder row: full-warp path
        const int b = batch[i];
        const float4* pg1 = reinterpret_cast<const float4*>(g1) + (size_t)b * D4;
        const float4* pg2 = reinterpret_cast<const float4*>(g2) + (size_t)b * D4;
        float4 u0 = pg1[lane], u1 = pg1[lane + 32];
        float4 w0 = pg2[lane], w1 = pg2[lane + 32];
        const float4* p1 = reinterpret_cast<const float4*>(h1) + (size_t)i * D4;
        const float4* p2 = reinterpret_cast<const float4*>(h2) + (size_t)i * D4;
        float4 x0 = __ldcs(p1 + lane), x1 = __ldcs(p1 + lane + 32);
        float4 y0 = __ldcs(p2 + lane), y1 = __ldcs(p2 + lane + 32);

        float sg1 = dot4(u0, u0) + dot4(u1, u1);
        float sg2 = dot4(w0, w0) + dot4(w1, w1);
        float d1  = dot4(x0, w0) + dot4(x1, w1);
        float s1  = dot4(x0, x0) + dot4(x1, x1);
        float d2  = dot4(y0, u0) + dot4(y1, u1);
        float s2  = dot4(y0, y0) + dot4(y1, y1);
#pragma unroll
        for (int off = 16; off > 0; off >>= 1) {
            sg1 += __shfl_xor_sync(0xffffffffu, sg1, off);
            sg2 += __shfl_xor_sync(0xffffffffu, sg2, off);
            d1  += __shfl_xor_sync(0xffffffffu, d1, off);
            s1  += __shfl_xor_sync(0xffffffffu, s1, off);
            d2  += __shfl_xor_sync(0xffffffffu, d2, off);
            s2  += __shfl_xor_sync(0xffffffffu, s2, off);
        }
        const float v = d1 * rsqrtf(fmaxf(s1, 1e-24f)) * rsqrtf(fmaxf(sg2, 1e-24f))
                      + d2 * rsqrtf(fmaxf(s2, 1e-24f)) * rsqrtf(fmaxf(sg1, 1e-24f));
        if (lane == 0) acc += (double)v;
    }

    // Fold lane16's accumulator into lane0 (other lanes hold 0.0).
    acc += __shfl_xor_sync(0xffffffffu, acc, 16);

    // ---- block-level partial ----
    __shared__ double sred[WPB];
    __shared__ bool   is_last;
    if (lane == 0) sred[wid] = acc;
    __syncthreads();
    if (threadIdx.x == 0) {
        double t = 0.0;
#pragma unroll
        for (int w = 0; w < WPB; ++w) t += sred[w];
        d_part[blockIdx.x] = t;
        __threadfence();
        unsigned prev = atomicAdd(&d_count, 1u);
        is_last = (prev == (unsigned)(NBLK - 1));
    }
    __syncthreads();

    // ---- last block: fixed-order deterministic final reduction ----
    if (is_last) {
        __shared__ double s[TPB];
        double t = 0.0;
        for (int k = threadIdx.x; k < NBLK; k += TPB)
            t += __ldcg(&d_part[k]);
        s[threadIdx.x] = t;
        __syncthreads();
#pragma unroll
        for (int off = TPB / 2; off > 0; off >>= 1) {
            if (threadIdx.x < off) s[threadIdx.x] += s[threadIdx.x + off];
            __syncthreads();
        }
        if (threadIdx.x == 0) {
            *out = (float)(s[0] / (double)G);
            d_count = 0;                   // reset for next graph replay
        }
    }
}

extern "C" void kernel_launch(void* const* d_in, const int* in_sizes, int n_in,
                              void* d_out, int out_size)
{
    const float* h1    = (const float*)d_in[0];
    const float* h2    = (const float*)d_in[1];
    const float* g1    = (const float*)d_in[2];
    const float* g2    = (const float*)d_in[3];
    const int*   batch = (const int*)d_in[4];   // jax default int32 (x64 disabled)

    const int N = in_sizes[4];          // rows in h1/h2
    const int G = in_sizes[2] / D;      // rows in g1/g2

    main_k<<<NBLK, TPB>>>(h1, h2, g1, g2, batch, (float*)d_out, N, G);
}